// round 12
// baseline (speedup 1.0000x reference)
#include <cuda_runtime.h>
#include <math.h>

#define B_SAMPLES 65536
#define D_DIM 512
#define WARPS_PER_BLOCK 8
#define THREADS (WARPS_PER_BLOCK * 32)
#define NUM_BLOCKS (B_SAMPLES / WARPS_PER_BLOCK)   // 8192
#define EPS 1e-8f

__device__ float        g_partials[NUM_BLOCKS];
__device__ unsigned int g_done_count = 0;

__global__ __launch_bounds__(THREADS)
void cos_loss_kernel(const float* __restrict__ emb,
                     const int* __restrict__ labels,
                     const float* __restrict__ proto,
                     float* __restrict__ out)
{
    const int warp_global = (blockIdx.x * WARPS_PER_BLOCK) + (threadIdx.x >> 5);
    const int lane = threadIdx.x & 31;
    const int wid  = threadIdx.x >> 5;

    // one warp per sample; lane 0 reads the (int32) label, broadcast
    int lab = 0;
    if (lane == 0) lab = labels[warp_global];
    lab = __shfl_sync(0xFFFFFFFFu, lab, 0);

    const float4* e = reinterpret_cast<const float4*>(emb + (size_t)warp_global * D_DIM);
    const float4* p = reinterpret_cast<const float4*>(proto + (size_t)lab * D_DIM);

    float dot = 0.f, ee = 0.f, pp = 0.f;
#pragma unroll
    for (int k = 0; k < 4; ++k) {
        float4 ev = e[lane + 32 * k];
        float4 pv = p[lane + 32 * k];
        dot = fmaf(ev.x, pv.x, dot); dot = fmaf(ev.y, pv.y, dot);
        dot = fmaf(ev.z, pv.z, dot); dot = fmaf(ev.w, pv.w, dot);
        ee  = fmaf(ev.x, ev.x, ee);  ee  = fmaf(ev.y, ev.y, ee);
        ee  = fmaf(ev.z, ev.z, ee);  ee  = fmaf(ev.w, ev.w, ee);
        pp  = fmaf(pv.x, pv.x, pp);  pp  = fmaf(pv.y, pv.y, pp);
        pp  = fmaf(pv.z, pv.z, pp);  pp  = fmaf(pv.w, pv.w, pp);
    }

#pragma unroll
    for (int o = 16; o > 0; o >>= 1) {
        dot += __shfl_xor_sync(0xFFFFFFFFu, dot, o);
        ee  += __shfl_xor_sync(0xFFFFFFFFu, ee,  o);
        pp  += __shfl_xor_sync(0xFFFFFFFFu, pp,  o);
    }

    __shared__ float s_cos[WARPS_PER_BLOCK];
    if (lane == 0) {
        float en = fmaxf(sqrtf(ee), EPS);
        float pn = fmaxf(sqrtf(pp), EPS);
        s_cos[wid] = dot / (en * pn);
    }
    __syncthreads();

    __shared__ bool s_is_last;
    if (threadIdx.x == 0) {
        float s = 0.f;
#pragma unroll
        for (int i = 0; i < WARPS_PER_BLOCK; ++i) s += s_cos[i];
        g_partials[blockIdx.x] = s;
        __threadfence();
        // atomicInc wraps to 0 on the last block -> counter is reset for the
        // next graph replay automatically.
        unsigned int prev = atomicInc(&g_done_count, NUM_BLOCKS - 1);
        s_is_last = (prev == NUM_BLOCKS - 1);
    }
    __syncthreads();

    // last block to finish performs the final deterministic reduction
    if (s_is_last) {
        const int tid = threadIdx.x;
        float s = 0.f;
#pragma unroll
        for (int i = 0; i < NUM_BLOCKS / THREADS; ++i)   // 32 iterations
            s += g_partials[tid + i * THREADS];

#pragma unroll
        for (int o = 16; o > 0; o >>= 1)
            s += __shfl_xor_sync(0xFFFFFFFFu, s, o);

        __shared__ float s_warp[WARPS_PER_BLOCK];
        if ((tid & 31) == 0) s_warp[tid >> 5] = s;
        __syncthreads();

        if (tid == 0) {
            float tot = 0.f;
#pragma unroll
            for (int i = 0; i < WARPS_PER_BLOCK; ++i) tot += s_warp[i];
            out[0] = 1.0f - tot / (float)B_SAMPLES;
        }
    }
}

extern "C" void kernel_launch(void* const* d_in, const int* in_sizes, int n_in,
                              void* d_out, int out_size)
{
    const float* emb    = (const float*)d_in[0];
    const int*   labels = (const int*)d_in[1];
    const float* proto  = (const float*)d_in[2];
    float*       out    = (float*)d_out;

    cos_loss_kernel<<<NUM_BLOCKS, THREADS>>>(emb, labels, proto, out);
}

// round 13
// speedup vs baseline: 1.5052x; 1.5052x over previous
#include <cuda_runtime.h>
#include <math.h>

#define B_SAMPLES 65536
#define D_DIM 512
#define WARPS_PER_BLOCK 8
#define THREADS (WARPS_PER_BLOCK * 32)
#define NUM_BLOCKS (B_SAMPLES / WARPS_PER_BLOCK)   // 8192
#define EPS 1e-8f

__device__ float g_partials[NUM_BLOCKS];

__global__ __launch_bounds__(THREADS)
void cos_partial_kernel(const float* __restrict__ emb,
                        const int* __restrict__ labels,
                        const float* __restrict__ proto)
{
    const int warp_global = (blockIdx.x * WARPS_PER_BLOCK) + (threadIdx.x >> 5);
    const int lane = threadIdx.x & 31;
    const int wid  = threadIdx.x >> 5;

    // one warp per sample; lane 0 reads the (int32) label, broadcast
    int lab = 0;
    if (lane == 0) lab = labels[warp_global];
    lab = __shfl_sync(0xFFFFFFFFu, lab, 0);

    const float4* e = reinterpret_cast<const float4*>(emb + (size_t)warp_global * D_DIM);
    const float4* p = reinterpret_cast<const float4*>(proto + (size_t)lab * D_DIM);

    float dot = 0.f, ee = 0.f, pp = 0.f;
#pragma unroll
    for (int k = 0; k < 4; ++k) {
        float4 ev = e[lane + 32 * k];
        float4 pv = p[lane + 32 * k];
        dot = fmaf(ev.x, pv.x, dot); dot = fmaf(ev.y, pv.y, dot);
        dot = fmaf(ev.z, pv.z, dot); dot = fmaf(ev.w, pv.w, dot);
        ee  = fmaf(ev.x, ev.x, ee);  ee  = fmaf(ev.y, ev.y, ee);
        ee  = fmaf(ev.z, ev.z, ee);  ee  = fmaf(ev.w, ev.w, ee);
        pp  = fmaf(pv.x, pv.x, pp);  pp  = fmaf(pv.y, pv.y, pp);
        pp  = fmaf(pv.z, pv.z, pp);  pp  = fmaf(pv.w, pv.w, pp);
    }

#pragma unroll
    for (int o = 16; o > 0; o >>= 1) {
        dot += __shfl_xor_sync(0xFFFFFFFFu, dot, o);
        ee  += __shfl_xor_sync(0xFFFFFFFFu, ee,  o);
        pp  += __shfl_xor_sync(0xFFFFFFFFu, pp,  o);
    }

    __shared__ float s_cos[WARPS_PER_BLOCK];
    if (lane == 0) {
        float en = fmaxf(sqrtf(ee), EPS);
        float pn = fmaxf(sqrtf(pp), EPS);
        s_cos[wid] = dot / (en * pn);
    }
    __syncthreads();

    if (threadIdx.x == 0) {
        float s = 0.f;
#pragma unroll
        for (int i = 0; i < WARPS_PER_BLOCK; ++i) s += s_cos[i];
        g_partials[blockIdx.x] = s;
    }
    // NO __threadfence here: visibility to the dependent kernel is guaranteed
    // by grid completion (implicit PDL trigger at kernel end).
}

__global__ __launch_bounds__(256)
void final_reduce_kernel(float* __restrict__ out)
{
    // PDL: this grid launches early (overlapping the primary's drain) and
    // blocks here until the primary grid completes. If the PDL attribute is
    // not honored, launch is simply serialized — identical semantics.
    cudaGridDependencySynchronize();

    const int tid = threadIdx.x;
    const float4* p4 = reinterpret_cast<const float4*>(g_partials);

    float s = 0.f;
#pragma unroll
    for (int i = 0; i < NUM_BLOCKS / 4 / 256; ++i) {   // 8 iterations of float4
        float4 v = p4[tid + i * 256];
        s += v.x + v.y + v.z + v.w;
    }

#pragma unroll
    for (int o = 16; o > 0; o >>= 1)
        s += __shfl_xor_sync(0xFFFFFFFFu, s, o);

    __shared__ float s_warp[8];
    if ((tid & 31) == 0) s_warp[tid >> 5] = s;
    __syncthreads();

    if (tid == 0) {
        float tot = 0.f;
#pragma unroll
        for (int i = 0; i < 8; ++i) tot += s_warp[i];
        out[0] = 1.0f - tot / (float)B_SAMPLES;
    }
}

extern "C" void kernel_launch(void* const* d_in, const int* in_sizes, int n_in,
                              void* d_out, int out_size)
{
    const float* emb    = (const float*)d_in[0];
    const int*   labels = (const int*)d_in[1];
    const float* proto  = (const float*)d_in[2];
    float*       out    = (float*)d_out;

    cos_partial_kernel<<<NUM_BLOCKS, THREADS>>>(emb, labels, proto);

    // Dependent launch with programmatic stream serialization: the reduce
    // kernel's launch latency overlaps the primary's execution/drain.
    cudaLaunchAttribute attrs[1];
    attrs[0].id = cudaLaunchAttributeProgrammaticStreamSerialization;
    attrs[0].val.programmaticStreamSerializationAllowed = 1;

    cudaLaunchConfig_t cfg = {};
    cfg.gridDim  = dim3(1, 1, 1);
    cfg.blockDim = dim3(256, 1, 1);
    cfg.dynamicSmemBytes = 0;
    cfg.stream = 0;
    cfg.attrs = attrs;
    cfg.numAttrs = 1;

    cudaLaunchKernelEx(&cfg, final_reduce_kernel, out);
}